// round 1
// baseline (speedup 1.0000x reference)
#include <cuda_runtime.h>
#include <cstdint>

#define NDIM 256
#define RP 2            // row-pairs per CTA (f32x2 packed) -> 4 rows per CTA

__device__ __forceinline__ void fma2(unsigned long long& d,
                                     unsigned long long a,
                                     unsigned long long b) {
    asm("fma.rn.f32x2 %0, %1, %2, %0;" : "+l"(d) : "l"(a), "l"(b));
}

__global__ void __launch_bounds__(256, 4)
clifford_kernel(const float* __restrict__ A,
                const float* __restrict__ B,
                float* __restrict__ out,
                int nrow) {
    __shared__ float2 As2[RP][NDIM];   // sign-folded A, 2 rows interleaved
    __shared__ float2 Bs2[RP][NDIM];   // B, 2 rows interleaved
    __shared__ unsigned char U8[NDIM]; // suffix-parity masks

    const unsigned tid = threadIdx.x;
    const int rowBase = blockIdx.x * (2 * RP);

    // --- fill phase: U_j, c_j fold, stage A/B rows ---
    {
        unsigned v = tid >> 1;
        v ^= v >> 1; v ^= v >> 2; v ^= v >> 4;
        const unsigned u = v & 0xffu;          // U_{j=tid}
        U8[tid] = (unsigned char)u;
        const float sg = (__popc(tid & u) & 1) ? -1.0f : 1.0f;  // fold c_j
        #pragma unroll
        for (int p = 0; p < RP; ++p) {
            const int r0 = rowBase + 2 * p;
            const float a0 = A[(size_t)r0 * NDIM + tid] * sg;
            const float a1 = A[(size_t)(r0 + 1) * NDIM + tid] * sg;
            As2[p][tid] = make_float2(a0, a1);
            Bs2[p][tid] = make_float2(B[(size_t)r0 * NDIM + tid],
                                      B[(size_t)(r0 + 1) * NDIM + tid]);
        }
    }
    __syncthreads();

    const unsigned i    = tid;
    const unsigned noti = (~i) & 0xffu;

    unsigned long long gp0 = 0ull, gp1 = 0ull;
    unsigned long long we0 = 0ull, we1 = 0ull;
    unsigned long long in0 = 0ull, in1 = 0ull;

    const unsigned long long* __restrict__ Ap0 =
        reinterpret_cast<const unsigned long long*>(&As2[0][0]);
    const unsigned long long* __restrict__ Ap1 =
        reinterpret_cast<const unsigned long long*>(&As2[1][0]);
    const unsigned long long* __restrict__ Bp0 =
        reinterpret_cast<const unsigned long long*>(&Bs2[0][0]);
    const unsigned long long* __restrict__ Bp1 =
        reinterpret_cast<const unsigned long long*>(&Bs2[1][0]);

    #pragma unroll 16
    for (int j = 0; j < NDIM; ++j) {
        const unsigned u   = U8[j];
        const unsigned s31 = (unsigned)__popc(i & u) << 31;          // parity bit -> sign bit
        const unsigned long long s64 =
            ((unsigned long long)s31 << 32) | (unsigned long long)s31;
        const unsigned x = i ^ (unsigned)j;

        const bool pw = ((unsigned)j & noti) == 0u;     // wedge: j subset of i
        const unsigned t = i & (unsigned)j;
        const bool pi = (t == 0u) | (t == i);           // inner: disjoint OR i subset of j

        // pair 0 (rows rowBase+0, rowBase+1)
        {
            const unsigned long long a = Ap0[j] ^ s64;
            const unsigned long long b = Bp0[x];
            fma2(gp0, a, b);
            if (pw) fma2(we0, a, b);
            if (pi) fma2(in0, a, b);
        }
        // pair 1 (rows rowBase+2, rowBase+3)
        {
            const unsigned long long a = Ap1[j] ^ s64;
            const unsigned long long b = Bp1[x];
            fma2(gp1, a, b);
            if (pw) fma2(we1, a, b);
            if (pi) fma2(in1, a, b);
        }
    }

    // --- store: out[prod][row][i], prod-stride = nrow*256 ---
    const size_t pstride = (size_t)nrow * NDIM;
    float* __restrict__ o = out;

    const unsigned glo0 = (unsigned)(gp0 & 0xffffffffull), ghi0 = (unsigned)(gp0 >> 32);
    const unsigned glo1 = (unsigned)(gp1 & 0xffffffffull), ghi1 = (unsigned)(gp1 >> 32);
    const unsigned wlo0 = (unsigned)(we0 & 0xffffffffull), whi0 = (unsigned)(we0 >> 32);
    const unsigned wlo1 = (unsigned)(we1 & 0xffffffffull), whi1 = (unsigned)(we1 >> 32);
    const unsigned ilo0 = (unsigned)(in0 & 0xffffffffull), ihi0 = (unsigned)(in0 >> 32);
    const unsigned ilo1 = (unsigned)(in1 & 0xffffffffull), ihi1 = (unsigned)(in1 >> 32);

    const size_t r0 = (size_t)rowBase * NDIM + i;
    o[0 * pstride + r0 + 0 * NDIM] = __uint_as_float(glo0);
    o[0 * pstride + r0 + 1 * NDIM] = __uint_as_float(ghi0);
    o[0 * pstride + r0 + 2 * NDIM] = __uint_as_float(glo1);
    o[0 * pstride + r0 + 3 * NDIM] = __uint_as_float(ghi1);

    o[1 * pstride + r0 + 0 * NDIM] = __uint_as_float(wlo0);
    o[1 * pstride + r0 + 1 * NDIM] = __uint_as_float(whi0);
    o[1 * pstride + r0 + 2 * NDIM] = __uint_as_float(wlo1);
    o[1 * pstride + r0 + 3 * NDIM] = __uint_as_float(whi1);

    o[2 * pstride + r0 + 0 * NDIM] = __uint_as_float(ilo0);
    o[2 * pstride + r0 + 1 * NDIM] = __uint_as_float(ihi0);
    o[2 * pstride + r0 + 2 * NDIM] = __uint_as_float(ilo1);
    o[2 * pstride + r0 + 3 * NDIM] = __uint_as_float(ihi1);
}

extern "C" void kernel_launch(void* const* d_in, const int* in_sizes, int n_in,
                              void* d_out, int out_size) {
    const float* A = (const float*)d_in[0];
    const float* B = (const float*)d_in[1];
    float* out = (float*)d_out;
    const int nrow = in_sizes[0] / NDIM;           // 1024
    const int nblk = nrow / (2 * RP);              // 256 CTAs
    clifford_kernel<<<nblk, 256>>>(A, B, out, nrow);
}

// round 3
// speedup vs baseline: 1.2653x; 1.2653x over previous
#include <cuda_runtime.h>
#include <cstdint>

using ull = unsigned long long;
#define NROW 1024
#define NDIM 256
#define ROWS 8          // rows per CTA
#define ICH  32         // i-chunk per CTA
#define JG   8          // j-interleave groups (one per warp)

__device__ __forceinline__ void fma2(ull& d, ull a, ull b) {
    asm("fma.rn.f32x2 %0, %1, %2, %0;" : "+l"(d) : "l"(a), "l"(b));
}
__device__ __forceinline__ ull mul2(ull a, ull b) {
    ull r; asm("mul.rn.f32x2 %0, %1, %2;" : "=l"(r) : "l"(a), "l"(b));
    return r;
}
// suffix-parity mask: bit p of Uof(j) = parity of bits of j strictly above p.
// XOR-linear: Uof(a^b) = Uof(a)^Uof(b).
__host__ __device__ constexpr unsigned Uof(unsigned j) {
    unsigned v = j >> 1; v ^= v >> 1; v ^= v >> 2; v ^= v >> 4;
    return v & 255u;
}

__global__ void __launch_bounds__(256)
clifford_kernel(const float* __restrict__ A, const float* __restrict__ B,
                float* __restrict__ out) {
    __shared__ float4 As[2][NDIM];          // sign-folded A, rows 0-3 / 4-7
    __shared__ float4 Bs[2][NDIM];
    __shared__ ull    stage[12][JG][ICH];   // reduction staging

    const unsigned tid = threadIdx.x;
    const unsigned gb  = blockIdx.x >> 3;   // row-group 0..127
    const unsigned ic  = blockIdx.x & 7;    // i-chunk   0..7
    const unsigned rowBase = gb * ROWS;
    const unsigned ibase   = ic * ICH;

    // ---- fill: thread tid stages component slot j = tid for all 8 rows ----
    {
        const unsigned j = tid;
        const float sg = (__popc(j & Uof(j)) & 1) ? -1.0f : 1.0f;
        float av[8], bv[8];
        #pragma unroll
        for (int r = 0; r < 8; ++r) {
            av[r] = A[(size_t)(rowBase + r) * NDIM + j] * sg;
            bv[r] = B[(size_t)(rowBase + r) * NDIM + j];
        }
        As[0][j] = make_float4(av[0], av[1], av[2], av[3]);
        As[1][j] = make_float4(av[4], av[5], av[6], av[7]);
        Bs[0][j] = make_float4(bv[0], bv[1], bv[2], bv[3]);
        Bs[1][j] = make_float4(bv[4], bv[5], bv[6], bv[7]);
    }
    __syncthreads();

    const unsigned il   = tid & 31;         // lane -> i within chunk
    const unsigned jg   = tid >> 5;         // warp -> j residue (mod 8)
    const unsigned i    = ibase + il;
    const unsigned noti = (~i) & 255u;

    // hoisted per-thread pieces of sign/masks (j = 8m | jg)
    const unsigned ph     = (unsigned)(__popc(i & Uof(jg)) & 1) << 31;
    const unsigned sgbase = 0x3f800000u ^ ph;   // ±1.0f base
    const unsigned g1     = jg & noti;          // low part of (j & ~i)
    const unsigned g2     = i & jg;             // low part of (i & j)

    ull acc[12];                                 // [prod*4 + pair]
    #pragma unroll
    for (int q = 0; q < 12; ++q) acc[q] = 0ull;

    const ulonglong2* __restrict__ As0 = reinterpret_cast<const ulonglong2*>(&As[0][0]);
    const ulonglong2* __restrict__ As1 = reinterpret_cast<const ulonglong2*>(&As[1][0]);
    const ulonglong2* __restrict__ Bs0 = reinterpret_cast<const ulonglong2*>(&Bs[0][0]);
    const ulonglong2* __restrict__ Bs1 = reinterpret_cast<const ulonglong2*>(&Bs[1][0]);

    #pragma unroll
    for (unsigned m = 0; m < 32; ++m) {
        const unsigned jh = 8u * m;            // compile-time constant
        const unsigned cU = Uof(jh);           // compile-time constant
        const unsigned j  = jh | jg;
        const unsigned x  = i ^ j;

        // sign = parity(i & U_j) split: const part + hoisted part
        const unsigned pc = (unsigned)__popc(i & cU);
        const unsigned sg = sgbase ^ (pc << 31);          // float bits of ±1

        // wedge: j subset of i;  inner: (i&j)==0 || (i&j)==i
        const bool pw = (((jh & noti) | g1) == 0u);
        const unsigned t = (i & jh) | g2;
        const bool pi = (t == 0u) | (t == i);
        const unsigned mw = pw ? sg : 0u;
        const unsigned mi = pi ? sg : 0u;

        const ull sg2 = ((ull)sg << 32) | sg;
        const ull mw2 = ((ull)mw << 32) | mw;
        const ull mi2 = ((ull)mi << 32) | mi;

        const ulonglong2 a0 = As0[j];   // broadcast (warp-uniform j)
        const ulonglong2 a1 = As1[j];
        const ulonglong2 b0 = Bs0[x];   // conflict-free lane permutation
        const ulonglong2 b1 = Bs1[x];

        ull t0 = mul2(a0.x, b0.x);
        fma2(acc[0], t0, sg2); fma2(acc[4], t0, mw2); fma2(acc[8],  t0, mi2);
        ull t1 = mul2(a0.y, b0.y);
        fma2(acc[1], t1, sg2); fma2(acc[5], t1, mw2); fma2(acc[9],  t1, mi2);
        ull t2 = mul2(a1.x, b1.x);
        fma2(acc[2], t2, sg2); fma2(acc[6], t2, mw2); fma2(acc[10], t2, mi2);
        ull t3 = mul2(a1.y, b1.y);
        fma2(acc[3], t3, sg2); fma2(acc[7], t3, mw2); fma2(acc[11], t3, mi2);
    }

    // ---- deterministic cross-warp reduction over the 8 j-groups ----
    #pragma unroll
    for (int q = 0; q < 12; ++q)
        stage[q][jg][il] = acc[q];
    __syncthreads();

    {
        const unsigned qh0 = (tid >> 5) * 3;        // 3 outputs per thread
        #pragma unroll
        for (int k = 0; k < 3; ++k) {
            const unsigned qh   = qh0 + k;          // 0..23 = prod*8 + row
            const unsigned prod = qh >> 3;
            const unsigned r    = qh & 7;
            const unsigned pair = r >> 1;
            const unsigned hf   = r & 1;
            const float* sp = reinterpret_cast<const float*>(&stage[prod * 4 + pair][0][0]);
            float s = 0.0f;
            #pragma unroll
            for (int w = 0; w < 8; ++w)
                s += sp[(w * ICH + il) * 2 + hf];
            out[(size_t)prod * (NROW * NDIM) + (size_t)(rowBase + r) * NDIM + ibase + il] = s;
        }
    }
}

extern "C" void kernel_launch(void* const* d_in, const int* in_sizes, int n_in,
                              void* d_out, int out_size) {
    const float* A = (const float*)d_in[0];
    const float* B = (const float*)d_in[1];
    float* out = (float*)d_out;
    // 1024 rows / 8 rows-per-CTA = 128 row-groups; x 8 i-chunks = 1024 CTAs
    clifford_kernel<<<1024, 256>>>(A, B, out);
}